// round 1
// baseline (speedup 1.0000x reference)
#include <cuda_runtime.h>
#include <math.h>

// Problem shape (fixed by the reference: x = [4, 4096, 64] fp32)
#define BN     4096      // points per batch
#define BD     64        // feature dim
#define NBATCH 4
#define TILE   128       // output tile edge
#define TPD    (BN / TILE)                 // 32 tiles per dim
#define PAIRS  (TPD * (TPD + 1) / 2)       // 528 upper-triangle tile pairs
#define TPB    256

#define SMEM_FLOATS (2 * BD * TILE + 2 * TILE)   // As + Bs + sqa + sqb = 16640
#define SMEM_BYTES  (SMEM_FLOATS * sizeof(float))

__device__ unsigned g_max_bits;
__device__ unsigned g_min_bits;

__global__ void hx_init() {
    g_max_bits = 0u;
    g_min_bits = 0x7F7FFFFFu;   // FLT_MAX bits
}

// Pass 1: per-tile distances (matmul identity, matching the reference formula),
// write raw distances to out, reduce global min/max.
__global__ __launch_bounds__(TPB) void hx_dist(const float* __restrict__ x,
                                               float* __restrict__ out) {
    extern __shared__ float sm[];
    float* As  = sm;                 // [BD][TILE] (k-major, transposed)
    float* Bs  = sm + BD * TILE;     // [BD][TILE]
    float* sqa = sm + 2 * BD * TILE; // [TILE]
    float* sqb = sqa + TILE;         // [TILE]

    const int tid = threadIdx.x;
    const int tx = tid & 15;
    const int ty = tid >> 4;

    // Decode block -> (batch, ti, tj) with ti <= tj
    int bidx = blockIdx.x;
    int b = bidx / PAIRS;
    int p = bidx - b * PAIRS;
    int ti = 0, span = TPD;
    while (p >= span) { p -= span; --span; ++ti; }
    int tj = ti + p;

    const float* xb = x + (size_t)b * BN * BD;

    // Load A and B row tiles (128 rows x 64 dims), transposed into [k][m].
    // m = tid&127 -> warp threads store consecutive m -> conflict-free STS.
    #pragma unroll
    for (int it = 0; it < 8; ++it) {
        int f  = it * TPB + tid;
        int m  = f & (TILE - 1);
        int d4 = f >> 7;             // 0..15 across the 8 iterations
        float4 va = *(const float4*)(xb + (size_t)(ti * TILE + m) * BD + d4 * 4);
        As[(d4 * 4 + 0) * TILE + m] = va.x;
        As[(d4 * 4 + 1) * TILE + m] = va.y;
        As[(d4 * 4 + 2) * TILE + m] = va.z;
        As[(d4 * 4 + 3) * TILE + m] = va.w;
        float4 vb = *(const float4*)(xb + (size_t)(tj * TILE + m) * BD + d4 * 4);
        Bs[(d4 * 4 + 0) * TILE + m] = vb.x;
        Bs[(d4 * 4 + 1) * TILE + m] = vb.y;
        Bs[(d4 * 4 + 2) * TILE + m] = vb.z;
        Bs[(d4 * 4 + 3) * TILE + m] = vb.w;
    }
    __syncthreads();

    // Row sums of squares for both tiles (threads 0..127 -> A, 128..255 -> B).
    {
        int m = tid & 127;
        const float* S = (tid < 128) ? As : Bs;
        float s = 0.f;
        #pragma unroll
        for (int k = 0; k < BD; ++k) {
            float v = S[k * TILE + m];
            s = fmaf(v, v, s);
        }
        if (tid < 128) sqa[m] = s; else sqb[m] = s;
    }
    __syncthreads();

    // 8x8 microtile Gram accumulation. Split fragments (tx*4 and 64+tx*4)
    // keep every LDS.128 conflict-free (quarter-warp spans 128 contiguous bytes).
    float acc[8][8];
    #pragma unroll
    for (int i = 0; i < 8; ++i)
        #pragma unroll
        for (int j = 0; j < 8; ++j) acc[i][j] = 0.f;

    #pragma unroll 8
    for (int k = 0; k < BD; ++k) {
        const float* Ak = As + k * TILE;
        const float* Bk = Bs + k * TILE;
        float4 a0 = *(const float4*)(Ak + ty * 4);
        float4 a1 = *(const float4*)(Ak + 64 + ty * 4);
        float4 b0 = *(const float4*)(Bk + tx * 4);
        float4 b1 = *(const float4*)(Bk + 64 + tx * 4);
        float av[8] = {a0.x, a0.y, a0.z, a0.w, a1.x, a1.y, a1.z, a1.w};
        float bv[8] = {b0.x, b0.y, b0.z, b0.w, b1.x, b1.y, b1.z, b1.w};
        #pragma unroll
        for (int i = 0; i < 8; ++i)
            #pragma unroll
            for (int j = 0; j < 8; ++j)
                acc[i][j] = fmaf(av[i], bv[j], acc[i][j]);
    }

    // Local row/col indices inside the tile for this thread's microtile.
    int rloc[8], cloc[8];
    #pragma unroll
    for (int i = 0; i < 8; ++i) rloc[i] = (i < 4) ? (ty * 4 + i) : (64 + ty * 4 + i - 4);
    #pragma unroll
    for (int j = 0; j < 8; ++j) cloc[j] = (j < 4) ? (tx * 4 + j) : (64 + tx * 4 + j - 4);

    // d = sqrt(max(0, sq_i + sq_j - 2*dot)) ; track min/max.
    float tmax = 0.f, tmin = 3.402823466e38f;
    #pragma unroll
    for (int i = 0; i < 8; ++i) {
        float ra = sqa[rloc[i]];
        #pragma unroll
        for (int j = 0; j < 8; ++j) {
            float d2 = ra + sqb[cloc[j]] - 2.f * acc[i][j];
            float d  = (d2 > 0.f) ? sqrtf(d2) : 0.f;
            acc[i][j] = d;
            tmax = fmaxf(tmax, d);
            tmin = fminf(tmin, d);
        }
    }

    float* ob = out + (size_t)b * BN * BN;

    // Direct tile write (float4, fully coalesced).
    #pragma unroll
    for (int i = 0; i < 8; ++i) {
        size_t rbase = (size_t)(ti * TILE + rloc[i]) * BN;
        #pragma unroll
        for (int h = 0; h < 2; ++h) {
            float4 v = make_float4(acc[i][h * 4 + 0], acc[i][h * 4 + 1],
                                   acc[i][h * 4 + 2], acc[i][h * 4 + 3]);
            *(float4*)(ob + rbase + tj * TILE + h * 64 + tx * 4) = v;
        }
    }
    // Mirror tile write (symmetry). 16B stores fill whole 32B sectors -> DRAM-efficient.
    if (ti != tj) {
        #pragma unroll
        for (int j = 0; j < 8; ++j) {
            size_t rbase = (size_t)(tj * TILE + cloc[j]) * BN;
            #pragma unroll
            for (int h = 0; h < 2; ++h) {
                float4 v = make_float4(acc[h * 4 + 0][j], acc[h * 4 + 1][j],
                                       acc[h * 4 + 2][j], acc[h * 4 + 3][j]);
                *(float4*)(ob + rbase + ti * TILE + h * 64 + ty * 4) = v;
            }
        }
    }

    // Warp-reduce min/max, one atomic per warp (nonneg floats: uint order == float order).
    #pragma unroll
    for (int off = 16; off; off >>= 1) {
        tmax = fmaxf(tmax, __shfl_xor_sync(0xffffffffu, tmax, off));
        tmin = fminf(tmin, __shfl_xor_sync(0xffffffffu, tmin, off));
    }
    if ((tid & 31) == 0) {
        atomicMax(&g_max_bits, __float_as_uint(tmax));
        atomicMin(&g_min_bits, __float_as_uint(tmin));
    }
}

// Pass 2: (d - min) / (max - min), diagonal := 1. Pure streaming, float4.
__global__ __launch_bounds__(256) void hx_norm(float* __restrict__ out) {
    int idx = blockIdx.x * 256 + threadIdx.x;   // float4 index, < 2^24
    float mn  = __uint_as_float(g_min_bits);
    float inv = 1.0f / (__uint_as_float(g_max_bits) - mn);
    float4 v = ((float4*)out)[idx];
    int e = idx << 2;                 // element index (< 2^27)
    int c = e & (BN - 1);             // column (aligned to 4)
    int r = (e >> 12) & (BN - 1);     // row (BN = 2^12)
    v.x = (v.x - mn) * inv;
    v.y = (v.y - mn) * inv;
    v.z = (v.z - mn) * inv;
    v.w = (v.w - mn) * inv;
    int dl = r - c;
    if ((unsigned)dl < 4u) ((float*)&v)[dl] = 1.0f;
    ((float4*)out)[idx] = v;
}

extern "C" void kernel_launch(void* const* d_in, const int* in_sizes, int n_in,
                              void* d_out, int out_size) {
    const float* x = (const float*)d_in[0];
    float* out = (float*)d_out;

    cudaFuncSetAttribute(hx_dist, cudaFuncAttributeMaxDynamicSharedMemorySize,
                         (int)SMEM_BYTES);

    hx_init<<<1, 1>>>();
    hx_dist<<<NBATCH * PAIRS, TPB, SMEM_BYTES>>>(x, out);

    int n4 = (NBATCH * BN * BN) / 4;          // 16,777,216 float4
    hx_norm<<<n4 / 256, 256>>>(out);
}

// round 3
// speedup vs baseline: 1.0348x; 1.0348x over previous
#include <cuda_runtime.h>
#include <math.h>

// Problem shape (fixed by the reference: x = [4, 4096, 64] fp32)
#define BN     4096      // points per batch
#define BD     64        // feature dim
#define NBATCH 4
#define TILE   128       // output tile edge
#define TPD    (BN / TILE)                 // 32 tiles per dim
#define PAIRS  (TPD * (TPD + 1) / 2)       // 528 upper-triangle tile pairs
#define TPB    256

#define SMEM_FLOATS (2 * BD * TILE + 2 * TILE)   // As + Bs + sqa + sqb = 16640
#define SMEM_BYTES  (SMEM_FLOATS * sizeof(float))

__device__ unsigned g_max_bits;   // bits of clamped d2 max (nonneg)
__device__ unsigned g_min_bits;   // bits of clamped d2 min (nonneg)

__global__ void hx_init() {
    g_max_bits = 0u;
    g_min_bits = 0x7F7FFFFFu;   // FLT_MAX bits
}

// ---- packed f32x2 helpers (Blackwell FFMA2 path, CC >= 10.0) -------------
__device__ __forceinline__ unsigned long long bcast2(float a) {
    unsigned long long r;
    asm("mov.b64 %0, {%1, %1};" : "=l"(r) : "f"(a));
    return r;
}
__device__ __forceinline__ unsigned long long pack2(float lo, float hi) {
    unsigned long long r;
    asm("mov.b64 %0, {%1, %2};" : "=l"(r) : "f"(lo), "f"(hi));
    return r;
}
__device__ __forceinline__ void fma2(unsigned long long& d,
                                     unsigned long long a, unsigned long long b) {
    asm("fma.rn.f32x2 %0, %1, %2, %0;" : "+l"(d) : "l"(a), "l"(b));
}
__device__ __forceinline__ void unpack2(unsigned long long v, float& lo, float& hi) {
    asm("mov.b64 {%0, %1}, %2;" : "=f"(lo), "=f"(hi) : "l"(v));
}

// MODE 0: reduce clamped-d2 min/max only (no gmem writes, no sqrt).
// MODE 1: recompute, normalize with global min/max, write tile + mirror,
//         diagonal := 1.
template <int MODE>
__global__ __launch_bounds__(TPB, 2) void hx_main(const float* __restrict__ x,
                                                  float* __restrict__ out) {
    extern __shared__ float sm[];
    float* As  = sm;                 // [BD][TILE] (k-major, transposed)
    float* Bs  = sm + BD * TILE;     // [BD][TILE]
    float* sqa = sm + 2 * BD * TILE; // [TILE]
    float* sqb = sqa + TILE;         // [TILE]

    const int tid = threadIdx.x;
    const int tx = tid & 15;
    const int ty = tid >> 4;

    // Decode block -> (batch, ti, tj) with ti <= tj
    int bidx = blockIdx.x;
    int b = bidx / PAIRS;
    int p = bidx - b * PAIRS;
    int ti = 0, span = TPD;
    while (p >= span) { p -= span; --span; ++ti; }
    int tj = ti + p;

    const float* xb = x + (size_t)b * BN * BD;

    // Load A and B row tiles (128 rows x 64 dims), transposed into [k][m].
    // m = tid&127 -> warp threads store consecutive m -> conflict-free STS.
    #pragma unroll
    for (int it = 0; it < 8; ++it) {
        int f  = it * TPB + tid;
        int m  = f & (TILE - 1);
        int d4 = f >> 7;             // 0..15
        float4 va = *(const float4*)(xb + (size_t)(ti * TILE + m) * BD + d4 * 4);
        As[(d4 * 4 + 0) * TILE + m] = va.x;
        As[(d4 * 4 + 1) * TILE + m] = va.y;
        As[(d4 * 4 + 2) * TILE + m] = va.z;
        As[(d4 * 4 + 3) * TILE + m] = va.w;
        float4 vb = *(const float4*)(xb + (size_t)(tj * TILE + m) * BD + d4 * 4);
        Bs[(d4 * 4 + 0) * TILE + m] = vb.x;
        Bs[(d4 * 4 + 1) * TILE + m] = vb.y;
        Bs[(d4 * 4 + 2) * TILE + m] = vb.z;
        Bs[(d4 * 4 + 3) * TILE + m] = vb.w;
    }
    __syncthreads();

    // Row sums of squares (threads 0..127 -> A, 128..255 -> B).
    {
        int m = tid & 127;
        const float* S = (tid < 128) ? As : Bs;
        float s = 0.f;
        #pragma unroll
        for (int k = 0; k < BD; ++k) {
            float v = S[k * TILE + m];
            s = fmaf(v, v, s);
        }
        if (tid < 128) sqa[m] = s; else sqb[m] = s;
    }
    __syncthreads();

    // 8x8 microtile Gram accumulation, packed as 8x4 f32x2 (FFMA2 — 2x the
    // scalar-FFMA rate on Blackwell). b-pairs come packed from LDS.128;
    // a values are broadcast-packed {a,a}. Split fragments (off 0 and 64)
    // keep every LDS.128 conflict-free.
    unsigned long long acc2[8][4];
    #pragma unroll
    for (int i = 0; i < 8; ++i)
        #pragma unroll
        for (int jp = 0; jp < 4; ++jp) acc2[i][jp] = 0ull;

    #pragma unroll 4
    for (int k = 0; k < BD; ++k) {
        const float* Ak = As + k * TILE;
        const float* Bk = Bs + k * TILE;
        float4 a0 = *(const float4*)(Ak + ty * 4);
        float4 a1 = *(const float4*)(Ak + 64 + ty * 4);
        float4 b0 = *(const float4*)(Bk + tx * 4);
        float4 b1 = *(const float4*)(Bk + 64 + tx * 4);
        unsigned long long A[8], B[4];
        A[0] = bcast2(a0.x); A[1] = bcast2(a0.y);
        A[2] = bcast2(a0.z); A[3] = bcast2(a0.w);
        A[4] = bcast2(a1.x); A[5] = bcast2(a1.y);
        A[6] = bcast2(a1.z); A[7] = bcast2(a1.w);
        B[0] = pack2(b0.x, b0.y); B[1] = pack2(b0.z, b0.w);
        B[2] = pack2(b1.x, b1.y); B[3] = pack2(b1.z, b1.w);
        #pragma unroll
        for (int i = 0; i < 8; ++i)
            #pragma unroll
            for (int jp = 0; jp < 4; ++jp)
                fma2(acc2[i][jp], A[i], B[jp]);
    }

    // Local row/col indices inside the tile for this thread's microtile.
    int rloc[8], cloc[8];
    #pragma unroll
    for (int i = 0; i < 8; ++i) rloc[i] = (i < 4) ? (ty * 4 + i) : (64 + ty * 4 + i - 4);
    #pragma unroll
    for (int j = 0; j < 8; ++j) cloc[j] = (j < 4) ? (tx * 4 + j) : (64 + tx * 4 + j - 4);

    if (MODE == 0) {
        // Reduce clamped d2 (min/max commute with the monotone sqrt-clamp).
        float tmax = 0.f, tmin = 3.402823466e38f;
        #pragma unroll
        for (int i = 0; i < 8; ++i) {
            float ra = sqa[rloc[i]];
            #pragma unroll
            for (int jp = 0; jp < 4; ++jp) {
                float dlo, dhi;
                unpack2(acc2[i][jp], dlo, dhi);
                float d2a = fmaf(-2.f, dlo, ra + sqb[cloc[2 * jp]]);
                float d2b = fmaf(-2.f, dhi, ra + sqb[cloc[2 * jp + 1]]);
                float ca = fmaxf(d2a, 0.f), cb = fmaxf(d2b, 0.f);
                tmax = fmaxf(tmax, fmaxf(ca, cb));
                tmin = fminf(tmin, fminf(ca, cb));
            }
        }
        #pragma unroll
        for (int off = 16; off; off >>= 1) {
            tmax = fmaxf(tmax, __shfl_xor_sync(0xffffffffu, tmax, off));
            tmin = fminf(tmin, __shfl_xor_sync(0xffffffffu, tmin, off));
        }
        if ((tid & 31) == 0) {
            atomicMax(&g_max_bits, __float_as_uint(tmax));
            atomicMin(&g_min_bits, __float_as_uint(tmin));
        }
    } else {
        // Normalization constants from the global clamped-d2 reduction.
        float d2min = __uint_as_float(g_min_bits);
        float d2max = __uint_as_float(g_max_bits);
        float mn  = (d2min > 0.f) ? sqrtf(d2min) : 0.f;
        float mx  = sqrtf(d2max);
        float inv = 1.0f / (mx - mn);

        // Convert dots -> normalized values in place (low register pressure).
        float vals[8][8];
        bool diag = (ti == tj);
        #pragma unroll
        for (int i = 0; i < 8; ++i) {
            float ra = sqa[rloc[i]];
            #pragma unroll
            for (int jp = 0; jp < 4; ++jp) {
                float dlo, dhi;
                unpack2(acc2[i][jp], dlo, dhi);
                float d2a = fmaf(-2.f, dlo, ra + sqb[cloc[2 * jp]]);
                float d2b = fmaf(-2.f, dhi, ra + sqb[cloc[2 * jp + 1]]);
                float da = (d2a > 0.f) ? sqrtf(d2a) : 0.f;
                float db = (d2b > 0.f) ? sqrtf(d2b) : 0.f;
                float va = (da - mn) * inv;
                float vb = (db - mn) * inv;
                if (diag && rloc[i] == cloc[2 * jp])     va = 1.0f;
                if (diag && rloc[i] == cloc[2 * jp + 1]) vb = 1.0f;
                vals[i][2 * jp]     = va;
                vals[i][2 * jp + 1] = vb;
            }
        }

        float* ob = out + (size_t)b * BN * BN;

        // Direct tile write (float4, fully coalesced).
        #pragma unroll
        for (int i = 0; i < 8; ++i) {
            size_t rbase = (size_t)(ti * TILE + rloc[i]) * BN;
            #pragma unroll
            for (int h = 0; h < 2; ++h) {
                float4 v = make_float4(vals[i][h * 4 + 0], vals[i][h * 4 + 1],
                                       vals[i][h * 4 + 2], vals[i][h * 4 + 3]);
                *(float4*)(ob + rbase + tj * TILE + h * 64 + tx * 4) = v;
            }
        }
        // Mirror tile write (symmetry). 16B stores fill whole 32B sectors.
        if (!diag) {
            #pragma unroll
            for (int j = 0; j < 8; ++j) {
                size_t rbase = (size_t)(tj * TILE + cloc[j]) * BN;
                #pragma unroll
                for (int h = 0; h < 2; ++h) {
                    float4 v = make_float4(vals[h * 4 + 0][j], vals[h * 4 + 1][j],
                                           vals[h * 4 + 2][j], vals[h * 4 + 3][j]);
                    *(float4*)(ob + rbase + ti * TILE + h * 64 + ty * 4) = v;
                }
            }
        }
    }
}

extern "C" void kernel_launch(void* const* d_in, const int* in_sizes, int n_in,
                              void* d_out, int out_size) {
    const float* x = (const float*)d_in[0];
    float* out = (float*)d_out;

    cudaFuncSetAttribute(hx_main<0>, cudaFuncAttributeMaxDynamicSharedMemorySize,
                         (int)SMEM_BYTES);
    cudaFuncSetAttribute(hx_main<1>, cudaFuncAttributeMaxDynamicSharedMemorySize,
                         (int)SMEM_BYTES);

    hx_init<<<1, 1>>>();
    hx_main<0><<<NBATCH * PAIRS, TPB, SMEM_BYTES>>>(x, out);   // global min/max of d2
    hx_main<1><<<NBATCH * PAIRS, TPB, SMEM_BYTES>>>(x, out);   // recompute + normalize + write
}

// round 8
// speedup vs baseline: 1.7656x; 1.7062x over previous
#include <cuda_runtime.h>
#include <cuda_bf16.h>
#include <math.h>
#include <stdint.h>

// Problem shape (fixed): x = [4, 4096, 64] fp32 -> out [4, 4096, 4096] fp32
#define BN    4096
#define BD    64
#define NB    4
#define TILE  128
#define TPD   (BN / TILE)                  // 32
#define PAIRS (TPD * (TPD + 1) / 2)        // 528
#define NBLK  (NB * PAIRS)                 // 2112 CTAs per pass
#define TPB   256

// SMEM layout (bytes). bf16 tiles use pitch 72 elems (144B) -> conflict-free
// fragment LDS (bank = 4*quad + t4). Mirror stage reuses the tile region.
#define SM_SQA   0                         // 128 fp32
#define SM_SQB   512                       // 128 fp32
#define SM_T     1024                      // 4 tiles x 128 x 144B = 73728
#define TILE_PITCH_B 144
#define TILE_BYTES   (128 * TILE_PITCH_B)  // 18432
#define SM_TOTAL (SM_T + 4 * TILE_BYTES)   // 74752
#define SM_STT   SM_T                      // fp32 [128][pitch 136] = 69632 (fits)
#define STT_PITCH 136

// ---- device globals (static scratch; no allocations) ----------------------
__device__ __nv_bfloat16 g_xhi[(size_t)NB * BN * BD];
__device__ __nv_bfloat16 g_xlo[(size_t)NB * BN * BD];
__device__ float    g_sq[NB * BN];
__device__ unsigned g_max_bits;
__device__ unsigned g_min_bits;

// ---- helpers ---------------------------------------------------------------
// m16n8k16 row.col bf16 MMA, fp32 accum (base PTX ISA, sm_80+; valid on sm_100)
__device__ __forceinline__ void mma16816(float* c, const unsigned* a, const unsigned* b) {
    asm volatile(
        "mma.sync.aligned.m16n8k16.row.col.f32.bf16.bf16.f32 "
        "{%0,%1,%2,%3}, {%4,%5,%6,%7}, {%8,%9}, {%0,%1,%2,%3};"
        : "+f"(c[0]), "+f"(c[1]), "+f"(c[2]), "+f"(c[3])
        : "r"(a[0]), "r"(a[1]), "r"(a[2]), "r"(a[3]), "r"(b[0]), "r"(b[1]));
}
__device__ __forceinline__ float rsqrt_a(float x) {
    float r;
    asm("rsqrt.approx.f32 %0, %1;" : "=f"(r) : "f"(x));
    return r;
}

// A fragment: rows (r, r+8), k cols (k0, k0+1, k0+8, k0+9) as bf16x2 words.
__device__ __forceinline__ void ldfragA(unsigned* f, const char* base, int r, int kb) {
    f[0] = *(const unsigned*)(base + (r)     * TILE_PITCH_B + kb);
    f[1] = *(const unsigned*)(base + (r + 8) * TILE_PITCH_B + kb);
    f[2] = *(const unsigned*)(base + (r)     * TILE_PITCH_B + kb + 16);
    f[3] = *(const unsigned*)(base + (r + 8) * TILE_PITCH_B + kb + 16);
}
// B fragment (col-major k16 x n8 == our row-major [n][k]): n row = q.
__device__ __forceinline__ void ldfragB(unsigned* f, const char* base, int n, int kb) {
    f[0] = *(const unsigned*)(base + (n) * TILE_PITCH_B + kb);
    f[1] = *(const unsigned*)(base + (n) * TILE_PITCH_B + kb + 16);
}

// ---- prep: split x into bf16 hi/lo, row sums of squares, init min/max -----
__global__ __launch_bounds__(256) void hx_prep(const float* __restrict__ x) {
    if (blockIdx.x == 0 && threadIdx.x == 0) {
        g_max_bits = 0u;
        g_min_bits = 0x7F7FFFFFu;
    }
    int f = blockIdx.x * 256 + threadIdx.x;          // float4 index
    float4 v = ((const float4*)x)[f];

    __nv_bfloat16 h0 = __float2bfloat16(v.x), h1 = __float2bfloat16(v.y);
    __nv_bfloat16 h2 = __float2bfloat16(v.z), h3 = __float2bfloat16(v.w);
    __nv_bfloat16 l0 = __float2bfloat16(v.x - __bfloat162float(h0));
    __nv_bfloat16 l1 = __float2bfloat16(v.y - __bfloat162float(h1));
    __nv_bfloat16 l2 = __float2bfloat16(v.z - __bfloat162float(h2));
    __nv_bfloat16 l3 = __float2bfloat16(v.w - __bfloat162float(h3));

    uint2 hp = make_uint2((unsigned)__bfloat16_as_ushort(h0) | ((unsigned)__bfloat16_as_ushort(h1) << 16),
                          (unsigned)__bfloat16_as_ushort(h2) | ((unsigned)__bfloat16_as_ushort(h3) << 16));
    uint2 lp = make_uint2((unsigned)__bfloat16_as_ushort(l0) | ((unsigned)__bfloat16_as_ushort(l1) << 16),
                          (unsigned)__bfloat16_as_ushort(l2) | ((unsigned)__bfloat16_as_ushort(l3) << 16));
    ((uint2*)g_xhi)[f] = hp;
    ((uint2*)g_xlo)[f] = lp;

    float s = v.x * v.x + v.y * v.y + v.z * v.z + v.w * v.w;
    #pragma unroll
    for (int o = 8; o; o >>= 1) s += __shfl_down_sync(0xffffffffu, s, o, 16);
    if ((threadIdx.x & 15) == 0) g_sq[f >> 4] = s;
}

// ---- main: HMMA Gram tile (bf16 hi/lo x3). MODE 0: min/max. MODE 1: write.
template <int MODE>
__global__ __launch_bounds__(TPB) void hx_mma(float* __restrict__ out) {
    extern __shared__ char smem[];
    const int tid  = threadIdx.x;
    const int wid  = tid >> 5;
    const int lane = tid & 31;
    const int q    = lane >> 2;    // 0..7
    const int t4   = lane & 3;     // 0..3
    const int wm   = wid >> 2;     // 0..1 : 64-row band
    const int wn   = wid & 3;      // 0..3 : 32-col band

    // Decode block -> (b, ti, tj), ti <= tj
    int bidx = blockIdx.x;
    int b = bidx / PAIRS;
    int p = bidx - b * PAIRS;
    int ti = 0, span = TPD;
    while (p >= span) { p -= span; --span; ++ti; }
    int tj = ti + p;
    const bool diag = (ti == tj);
    const int tibase = ti * TILE, tjbase = tj * TILE;

    float mn = 0.f, inv = 0.f;
    if (MODE == 1) {   // read early; set by pass 0 (launch-ordered)
        float d2min = __uint_as_float(g_min_bits);
        float d2max = __uint_as_float(g_max_bits);
        mn = (d2min > 0.f) ? d2min * rsqrt_a(d2min) : 0.f;
        inv = 1.0f / (d2max * rsqrt_a(d2max) - mn);
    }

    // Load 4 bf16 tiles: t0=Ahi t1=Alo t2=Bhi t3=Blo, [128 rows][64 k], pitch 144B.
    #pragma unroll
    for (int it = 0; it < 16; ++it) {
        int idx = it * TPB + tid;            // 0..4095
        int t   = idx >> 10;
        int rem = idx & 1023;
        int row = rem >> 3;
        int ch  = rem & 7;
        const __nv_bfloat16* src = (t & 1) ? g_xlo : g_xhi;
        int row0 = ((t < 2) ? ti : tj) * TILE;
        uint4 v = *(const uint4*)(src + ((size_t)b * BN + row0 + row) * BD + ch * 8);
        *(uint4*)(smem + SM_T + t * TILE_BYTES + row * TILE_PITCH_B + ch * 16) = v;
    }
    if (tid < 128)       ((float*)(smem + SM_SQA))[tid]       = g_sq[b * BN + tibase + tid];
    else                 ((float*)(smem + SM_SQB))[tid - 128] = g_sq[b * BN + tjbase + tid - 128];
    __syncthreads();

    const char* tAh = smem + SM_T;
    const char* tAl = tAh + TILE_BYTES;
    const char* tBh = tAl + TILE_BYTES;
    const char* tBl = tBh + TILE_BYTES;

    float acc[4][4][4];
    #pragma unroll
    for (int i = 0; i < 4; ++i)
        #pragma unroll
        for (int j = 0; j < 4; ++j)
            #pragma unroll
            for (int e = 0; e < 4; ++e) acc[i][j][e] = 0.f;

    // Mainloop: 4 k16-chunks x (hi*hi + hi*lo + lo*hi) x 16 tiles = 192 HMMA.
    #pragma unroll
    for (int kc = 0; kc < 4; ++kc) {
        const int kb = kc * 32 + t4 * 4;   // byte offset of this thread's k pair
        unsigned Ah[4][4], Al[4][4], Bh[4][2], Bl[4][2];
        #pragma unroll
        for (int mt = 0; mt < 4; ++mt) ldfragA(Ah[mt], tAh, wm * 64 + mt * 16 + q, kb);
        #pragma unroll
        for (int nt = 0; nt < 4; ++nt) ldfragB(Bh[nt], tBh, wn * 32 + nt * 8 + q, kb);
        #pragma unroll
        for (int mt = 0; mt < 4; ++mt)
            #pragma unroll
            for (int nt = 0; nt < 4; ++nt) mma16816(acc[mt][nt], Ah[mt], Bh[nt]);
        #pragma unroll
        for (int nt = 0; nt < 4; ++nt) ldfragB(Bl[nt], tBl, wn * 32 + nt * 8 + q, kb);
        #pragma unroll
        for (int mt = 0; mt < 4; ++mt)
            #pragma unroll
            for (int nt = 0; nt < 4; ++nt) mma16816(acc[mt][nt], Ah[mt], Bl[nt]);
        #pragma unroll
        for (int mt = 0; mt < 4; ++mt) ldfragA(Al[mt], tAl, wm * 64 + mt * 16 + q, kb);
        #pragma unroll
        for (int mt = 0; mt < 4; ++mt)
            #pragma unroll
            for (int nt = 0; nt < 4; ++nt) mma16816(acc[mt][nt], Al[mt], Bh[nt]);
    }

    // Per-thread row/col sums of squares.
    const float* sqa = (const float*)(smem + SM_SQA);
    const float* sqb = (const float*)(smem + SM_SQB);
    float sr0[4], sr1[4], sc0[4], sc1[4];
    #pragma unroll
    for (int mt = 0; mt < 4; ++mt) {
        sr0[mt] = sqa[wm * 64 + mt * 16 + q];
        sr1[mt] = sqa[wm * 64 + mt * 16 + q + 8];
    }
    #pragma unroll
    for (int nt = 0; nt < 4; ++nt) {
        sc0[nt] = sqb[wn * 32 + nt * 8 + t4 * 2];
        sc1[nt] = sqb[wn * 32 + nt * 8 + t4 * 2 + 1];
    }

    if (MODE == 0) {
        float tmax = 0.f, tmin = 3.402823466e38f;
        #pragma unroll
        for (int mt = 0; mt < 4; ++mt)
            #pragma unroll
            for (int nt = 0; nt < 4; ++nt) {
                float d00 = fmaxf(fmaf(-2.f, acc[mt][nt][0], sr0[mt] + sc0[nt]), 0.f);
                float d01 = fmaxf(fmaf(-2.f, acc[mt][nt][1], sr0[mt] + sc1[nt]), 0.f);
                float d10 = fmaxf(fmaf(-2.f, acc[mt][nt][2], sr1[mt] + sc0[nt]), 0.f);
                float d11 = fmaxf(fmaf(-2.f, acc[mt][nt][3], sr1[mt] + sc1[nt]), 0.f);
                tmax = fmaxf(tmax, fmaxf(fmaxf(d00, d01), fmaxf(d10, d11)));
                tmin = fminf(tmin, fminf(fminf(d00, d01), fminf(d10, d11)));
            }
        #pragma unroll
        for (int o = 16; o; o >>= 1) {
            tmax = fmaxf(tmax, __shfl_xor_sync(0xffffffffu, tmax, o));
            tmin = fminf(tmin, __shfl_xor_sync(0xffffffffu, tmin, o));
        }
        if (lane == 0) {
            atomicMax(&g_max_bits, __float_as_uint(tmax));
            atomicMin(&g_min_bits, __float_as_uint(tmin));
        }
        return;
    }

    // MODE 1: normalize in registers (overwrite acc with v), store main tile,
    // then stage transposed in SMEM and store the mirror coalesced.
    float* ob = out + (size_t)b * BN * BN;
    #pragma unroll
    for (int mt = 0; mt < 4; ++mt) {
        int r0 = wm * 64 + mt * 16 + q, r1 = r0 + 8;
        #pragma unroll
        for (int nt = 0; nt < 4; ++nt) {
            int c0 = wn * 32 + nt * 8 + t4 * 2;
            float d2, d;
            d2 = fmaf(-2.f, acc[mt][nt][0], sr0[mt] + sc0[nt]);
            d  = (d2 > 0.f) ? d2 * rsqrt_a(d2) : 0.f;
            acc[mt][nt][0] = (diag && r0 == c0)     ? 1.0f : (d - mn) * inv;
            d2 = fmaf(-2.f, acc[mt][nt][1], sr0[mt] + sc1[nt]);
            d  = (d2 > 0.f) ? d2 * rsqrt_a(d2) : 0.f;
            acc[mt][nt][1] = (diag && r0 == c0 + 1) ? 1.0f : (d - mn) * inv;
            d2 = fmaf(-2.f, acc[mt][nt][2], sr1[mt] + sc0[nt]);
            d  = (d2 > 0.f) ? d2 * rsqrt_a(d2) : 0.f;
            acc[mt][nt][2] = (diag && r1 == c0)     ? 1.0f : (d - mn) * inv;
            d2 = fmaf(-2.f, acc[mt][nt][3], sr1[mt] + sc1[nt]);
            d  = (d2 > 0.f) ? d2 * rsqrt_a(d2) : 0.f;
            acc[mt][nt][3] = (diag && r1 == c0 + 1) ? 1.0f : (d - mn) * inv;
            // Main-tile stores: 8B, 32B-sector aligned across the quad.
            *(float2*)(ob + (size_t)(tibase + r0) * BN + tjbase + c0) =
                make_float2(acc[mt][nt][0], acc[mt][nt][1]);
            *(float2*)(ob + (size_t)(tibase + r1) * BN + tjbase + c0) =
                make_float2(acc[mt][nt][2], acc[mt][nt][3]);
        }
    }

    if (!diag) {
        __syncthreads();                     // tiles dead -> reuse as stage
        float* st = (float*)(smem + SM_STT); // [col][row], pitch 136
        #pragma unroll
        for (int mt = 0; mt < 4; ++mt) {
            int r0 = wm * 64 + mt * 16 + q, r1 = r0 + 8;
            #pragma unroll
            for (int nt = 0; nt < 4; ++nt) {
                int c0 = wn * 32 + nt * 8 + t4 * 2;
                st[(c0)     * STT_PITCH + r0] = acc[mt][nt][0];
                st[(c0 + 1) * STT_PITCH + r0] = acc[mt][nt][1];
                st[(c0)     * STT_PITCH + r1] = acc[mt][nt][2];
                st[(c0 + 1) * STT_PITCH + r1] = acc[mt][nt][3];
            }
        }
        __syncthreads();
        // Mirror rows: per warp one row (mc), lanes cover 128 floats (LDS.128
        // conflict-free: word = mc*136 + 4*lane).
        #pragma unroll
        for (int i = 0; i < 16; ++i) {
            int idx = i * TPB + tid;
            int mc = idx >> 5, g = idx & 31;
            float4 w = *(const float4*)(st + mc * STT_PITCH + g * 4);
            *(float4*)(ob + (size_t)(tjbase + mc) * BN + tibase + g * 4) = w;
        }
    }
}

extern "C" void kernel_launch(void* const* d_in, const int* in_sizes, int n_in,
                              void* d_out, int out_size) {
    const float* x = (const float*)d_in[0];
    float* out = (float*)d_out;

    cudaFuncSetAttribute(hx_mma<0>, cudaFuncAttributeMaxDynamicSharedMemorySize, SM_TOTAL);
    cudaFuncSetAttribute(hx_mma<1>, cudaFuncAttributeMaxDynamicSharedMemorySize, SM_TOTAL);

    hx_prep<<<(NB * BN * BD / 4) / 256, 256>>>(x);     // split + sq + init
    hx_mma<0><<<NBLK, TPB, SM_TOTAL>>>(out);           // global min/max of d2
    hx_mma<1><<<NBLK, TPB, SM_TOTAL>>>(out);           // recompute + normalize + write
}

// round 9
// speedup vs baseline: 2.7957x; 1.5834x over previous
#include <cuda_runtime.h>
#include <cuda_fp16.h>
#include <math.h>
#include <stdint.h>

// Problem shape (fixed): x = [4, 4096, 64] fp32 -> out [4, 4096, 4096] fp32
#define BN    4096
#define BD    64
#define NB    4
#define TILE  128
#define TPD   (BN / TILE)                  // 32
#define PAIRS (TPD * (TPD + 1) / 2)        // 528
#define NBLK  (NB * PAIRS)                 // 2112 CTAs per pass
#define TPB   256

// SMEM layout (bytes). fp16 tiles use pitch 72 halves (144B) -> conflict-free
// fragment LDS. Mirror stage reuses the tile region (both dead post-MMA).
#define SM_SQA   0                         // 128 fp32
#define SM_SQB   512                       // 128 fp32
#define SM_T     1024                      // 2 tiles x 128 x 144B
#define TILE_PITCH_B 144
#define TILE_BYTES   (128 * TILE_PITCH_B)  // 18432
#define SM_STT   SM_T                      // fp32 [128][pitch 136] = 69632
#define STT_PITCH 136
#define SM_TOTAL (1024 + 69632)            // 70656 (stage > 2 tiles)

// ---- device globals (static scratch; no allocations) ----------------------
__device__ __half  g_xh[(size_t)NB * BN * BD];
__device__ float    g_sq[NB * BN];
__device__ unsigned g_max_bits;
__device__ unsigned g_min_bits;

// ---- helpers ---------------------------------------------------------------
// m16n8k16 row.col fp16 MMA, fp32 accum (base PTX ISA since sm_80; ok on sm_100)
__device__ __forceinline__ void mma16816(float* c, const unsigned* a, const unsigned* b) {
    asm volatile(
        "mma.sync.aligned.m16n8k16.row.col.f32.f16.f16.f32 "
        "{%0,%1,%2,%3}, {%4,%5,%6,%7}, {%8,%9}, {%0,%1,%2,%3};"
        : "+f"(c[0]), "+f"(c[1]), "+f"(c[2]), "+f"(c[3])
        : "r"(a[0]), "r"(a[1]), "r"(a[2]), "r"(a[3]), "r"(b[0]), "r"(b[1]));
}
__device__ __forceinline__ float rsqrt_a(float x) {
    float r;
    asm("rsqrt.approx.f32 %0, %1;" : "=f"(r) : "f"(x));
    return r;
}
// A fragment: rows (r, r+8), k halves (2*t4, 2*t4+1, +8, +9).
__device__ __forceinline__ void ldfragA(unsigned* f, const char* base, int r, int kb) {
    f[0] = *(const unsigned*)(base + (r)     * TILE_PITCH_B + kb);
    f[1] = *(const unsigned*)(base + (r + 8) * TILE_PITCH_B + kb);
    f[2] = *(const unsigned*)(base + (r)     * TILE_PITCH_B + kb + 16);
    f[3] = *(const unsigned*)(base + (r + 8) * TILE_PITCH_B + kb + 16);
}
__device__ __forceinline__ void ldfragB(unsigned* f, const char* base, int n, int kb) {
    f[0] = *(const unsigned*)(base + (n) * TILE_PITCH_B + kb);
    f[1] = *(const unsigned*)(base + (n) * TILE_PITCH_B + kb + 16);
}

// ---- prep: x -> fp16, row sums of squares (fp32), init min/max -------------
__global__ __launch_bounds__(256) void hx_prep(const float* __restrict__ x) {
    if (blockIdx.x == 0 && threadIdx.x == 0) {
        g_max_bits = 0u;
        g_min_bits = 0x7F7FFFFFu;
    }
    int f = blockIdx.x * 256 + threadIdx.x;          // float4 index
    float4 v = ((const float4*)x)[f];

    __half2 p0 = __floats2half2_rn(v.x, v.y);
    __half2 p1 = __floats2half2_rn(v.z, v.w);
    ((uint2*)g_xh)[f] = make_uint2(*(unsigned*)&p0, *(unsigned*)&p1);

    float s = v.x * v.x + v.y * v.y + v.z * v.z + v.w * v.w;
    #pragma unroll
    for (int o = 8; o; o >>= 1) s += __shfl_down_sync(0xffffffffu, s, o, 16);
    if ((threadIdx.x & 15) == 0) g_sq[f >> 4] = s;
}

// ---- main: single-term fp16 HMMA Gram tile. MODE 0: min/max. MODE 1: write.
template <int MODE>
__global__ __launch_bounds__(TPB) void hx_mma(float* __restrict__ out) {
    extern __shared__ char smem[];
    const int tid  = threadIdx.x;
    const int wid  = tid >> 5;
    const int lane = tid & 31;
    const int q    = lane >> 2;    // 0..7
    const int t4   = lane & 3;     // 0..3
    const int wm   = wid >> 2;     // 0..1 : 64-row band
    const int wn   = wid & 3;      // 0..3 : 32-col band

    // Decode block -> (b, ti, tj), ti <= tj
    int bidx = blockIdx.x;
    int b = bidx / PAIRS;
    int p = bidx - b * PAIRS;
    int ti = 0, span = TPD;
    while (p >= span) { p -= span; --span; ++ti; }
    int tj = ti + p;
    const bool diag = (ti == tj);
    const int tibase = ti * TILE, tjbase = tj * TILE;

    float mn = 0.f, inv = 0.f;
    if (MODE == 1) {   // constants from pass 0 (launch-ordered)
        float d2min = __uint_as_float(g_min_bits);
        float d2max = __uint_as_float(g_max_bits);
        mn = (d2min > 0.f) ? d2min * rsqrt_a(d2min) : 0.f;
        inv = 1.0f / (d2max * rsqrt_a(d2max) - mn);
    }

    // Load 2 fp16 tiles (A rows ti*128.., B rows tj*128..), [128][64], pitch 144B.
    #pragma unroll
    for (int it = 0; it < 8; ++it) {
        int idx = it * TPB + tid;            // 0..2047
        int t   = idx >> 10;                 // 0 = A, 1 = B
        int rem = idx & 1023;
        int row = rem >> 3;
        int ch  = rem & 7;
        int row0 = (t ? tj : ti) * TILE;
        uint4 v = *(const uint4*)(g_xh + ((size_t)b * BN + row0 + row) * BD + ch * 8);
        *(uint4*)(smem + SM_T + t * TILE_BYTES + row * TILE_PITCH_B + ch * 16) = v;
    }
    if (tid < 128)       ((float*)(smem + SM_SQA))[tid]       = g_sq[b * BN + tibase + tid];
    else                 ((float*)(smem + SM_SQB))[tid - 128] = g_sq[b * BN + tjbase + tid - 128];
    __syncthreads();

    const char* tA = smem + SM_T;
    const char* tB = tA + TILE_BYTES;

    float acc[4][4][4];
    #pragma unroll
    for (int i = 0; i < 4; ++i)
        #pragma unroll
        for (int j = 0; j < 4; ++j)
            #pragma unroll
            for (int e = 0; e < 4; ++e) acc[i][j][e] = 0.f;

    // Mainloop: 4 k16-chunks x 16 m16n8 tiles = 64 HMMA per warp.
    #pragma unroll
    for (int kc = 0; kc < 4; ++kc) {
        const int kb = kc * 32 + t4 * 4;
        unsigned A[4][4], B[4][2];
        #pragma unroll
        for (int mt = 0; mt < 4; ++mt) ldfragA(A[mt], tA, wm * 64 + mt * 16 + q, kb);
        #pragma unroll
        for (int nt = 0; nt < 4; ++nt) ldfragB(B[nt], tB, wn * 32 + nt * 8 + q, kb);
        #pragma unroll
        for (int mt = 0; mt < 4; ++mt)
            #pragma unroll
            for (int nt = 0; nt < 4; ++nt) mma16816(acc[mt][nt], A[mt], B[nt]);
    }

    // Per-thread row/col sums of squares.
    const float* sqa = (const float*)(smem + SM_SQA);
    const float* sqb = (const float*)(smem + SM_SQB);
    float sr0[4], sr1[4], sc0[4], sc1[4];
    #pragma unroll
    for (int mt = 0; mt < 4; ++mt) {
        sr0[mt] = sqa[wm * 64 + mt * 16 + q];
        sr1[mt] = sqa[wm * 64 + mt * 16 + q + 8];
    }
    #pragma unroll
    for (int nt = 0; nt < 4; ++nt) {
        sc0[nt] = sqb[wn * 32 + nt * 8 + t4 * 2];
        sc1[nt] = sqb[wn * 32 + nt * 8 + t4 * 2 + 1];
    }

    if (MODE == 0) {
        float tmax = 0.f, tmin = 3.402823466e38f;
        #pragma unroll
        for (int mt = 0; mt < 4; ++mt)
            #pragma unroll
            for (int nt = 0; nt < 4; ++nt) {
                float d00 = fmaxf(fmaf(-2.f, acc[mt][nt][0], sr0[mt] + sc0[nt]), 0.f);
                float d01 = fmaxf(fmaf(-2.f, acc[mt][nt][1], sr0[mt] + sc1[nt]), 0.f);
                float d10 = fmaxf(fmaf(-2.f, acc[mt][nt][2], sr1[mt] + sc0[nt]), 0.f);
                float d11 = fmaxf(fmaf(-2.f, acc[mt][nt][3], sr1[mt] + sc1[nt]), 0.f);
                tmax = fmaxf(tmax, fmaxf(fmaxf(d00, d01), fmaxf(d10, d11)));
                tmin = fminf(tmin, fminf(fminf(d00, d01), fminf(d10, d11)));
            }
        #pragma unroll
        for (int o = 16; o; o >>= 1) {
            tmax = fmaxf(tmax, __shfl_xor_sync(0xffffffffu, tmax, o));
            tmin = fminf(tmin, __shfl_xor_sync(0xffffffffu, tmin, o));
        }
        if (lane == 0) {
            atomicMax(&g_max_bits, __float_as_uint(tmax));
            atomicMin(&g_min_bits, __float_as_uint(tmin));
        }
        return;
    }

    // MODE 1: normalize in registers, store main tile, stage + store mirror.
    float* ob = out + (size_t)b * BN * BN;
    #pragma unroll
    for (int mt = 0; mt < 4; ++mt) {
        int r0 = wm * 64 + mt * 16 + q, r1 = r0 + 8;
        #pragma unroll
        for (int nt = 0; nt < 4; ++nt) {
            int c0 = wn * 32 + nt * 8 + t4 * 2;
            float d2, d;
            d2 = fmaf(-2.f, acc[mt][nt][0], sr0[mt] + sc0[nt]);
            d  = (d2 > 0.f) ? d2 * rsqrt_a(d2) : 0.f;
            acc[mt][nt][0] = (diag && r0 == c0)     ? 1.0f : (d - mn) * inv;
            d2 = fmaf(-2.f, acc[mt][nt][1], sr0[mt] + sc1[nt]);
            d  = (d2 > 0.f) ? d2 * rsqrt_a(d2) : 0.f;
            acc[mt][nt][1] = (diag && r0 == c0 + 1) ? 1.0f : (d - mn) * inv;
            d2 = fmaf(-2.f, acc[mt][nt][2], sr1[mt] + sc0[nt]);
            d  = (d2 > 0.f) ? d2 * rsqrt_a(d2) : 0.f;
            acc[mt][nt][2] = (diag && r1 == c0)     ? 1.0f : (d - mn) * inv;
            d2 = fmaf(-2.f, acc[mt][nt][3], sr1[mt] + sc1[nt]);
            d  = (d2 > 0.f) ? d2 * rsqrt_a(d2) : 0.f;
            acc[mt][nt][3] = (diag && r1 == c0 + 1) ? 1.0f : (d - mn) * inv;
            *(float2*)(ob + (size_t)(tibase + r0) * BN + tjbase + c0) =
                make_float2(acc[mt][nt][0], acc[mt][nt][1]);
            *(float2*)(ob + (size_t)(tibase + r1) * BN + tjbase + c0) =
                make_float2(acc[mt][nt][2], acc[mt][nt][3]);
        }
    }

    if (!diag) {
        __syncthreads();                     // tiles dead -> reuse as stage
        float* st = (float*)(smem + SM_STT); // [col][row], pitch 136
        #pragma unroll
        for (int mt = 0; mt < 4; ++mt) {
            int r0 = wm * 64 + mt * 16 + q, r1 = r0 + 8;
            #pragma unroll
            for (int nt = 0; nt < 4; ++nt) {
                int c0 = wn * 32 + nt * 8 + t4 * 2;
                st[(c0)     * STT_PITCH + r0] = acc[mt][nt][0];
                st[(c0 + 1) * STT_PITCH + r0] = acc[mt][nt][1];
                st[(c0)     * STT_PITCH + r1] = acc[mt][nt][2];
                st[(c0 + 1) * STT_PITCH + r1] = acc[mt][nt][3];
            }
        }
        __syncthreads();
        #pragma unroll
        for (int i = 0; i < 16; ++i) {
            int idx = i * TPB + tid;
            int mc = idx >> 5, g = idx & 31;
            float4 w = *(const float4*)(st + mc * STT_PITCH + g * 4);
            *(float4*)(ob + (size_t)(tjbase + mc) * BN + tibase + g * 4) = w;
        }
    }
}

extern "C" void kernel_launch(void* const* d_in, const int* in_sizes, int n_in,
                              void* d_out, int out_size) {
    const float* x = (const float*)d_in[0];
    float* out = (float*)d_out;

    cudaFuncSetAttribute(hx_mma<0>, cudaFuncAttributeMaxDynamicSharedMemorySize, SM_TOTAL);
    cudaFuncSetAttribute(hx_mma<1>, cudaFuncAttributeMaxDynamicSharedMemorySize, SM_TOTAL);

    hx_prep<<<(NB * BN * BD / 4) / 256, 256>>>(x);     // fp16 convert + sq + init
    hx_mma<0><<<NBLK, TPB, SM_TOTAL>>>(out);           // global min/max of d2
    hx_mma<1><<<NBLK, TPB, SM_TOTAL>>>(out);           // recompute + normalize + write
}

// round 10
// speedup vs baseline: 2.8120x; 1.0058x over previous
#include <cuda_runtime.h>
#include <cuda_fp16.h>
#include <math.h>
#include <stdint.h>

// Problem shape (fixed): x = [4, 4096, 64] fp32 -> out [4, 4096, 4096] fp32
#define BN    4096
#define BD    64
#define NB    4
#define TILE  128
#define TPD   (BN / TILE)                  // 32
#define PAIRS (TPD * (TPD + 1) / 2)        // 528
#define NBLK  (NB * PAIRS)                 // 2112 CTAs per pass
#define TPB   256

// SMEM layout (bytes). fp16 tiles use pitch 72 halves (144B) -> conflict-free
// ldmatrix (bank = 4*row mod 32, 16B lanes). Mirror stage reuses tile region.
#define SM_SQA   0                         // 128 fp32
#define SM_SQB   512                       // 128 fp32
#define SM_T     1024                      // 2 tiles x 128 x 144B
#define TILE_PITCH_B 144
#define TILE_BYTES   (128 * TILE_PITCH_B)  // 18432
#define SM_STT   SM_T                      // fp32 [128][pitch 136] = 69632
#define STT_PITCH 136
#define SM_TOTAL (1024 + 69632)            // 70656

// ---- device globals (static scratch; no allocations) ----------------------
__device__ __half  g_xh[(size_t)NB * BN * BD];
__device__ float    g_sq[NB * BN];
__device__ unsigned g_max_bits;
__device__ unsigned g_min_bits;

// ---- helpers ---------------------------------------------------------------
// m16n8k16 row.col fp16 MMA, fp32 accum (base PTX ISA since sm_80)
__device__ __forceinline__ void mma16816(float* c, const unsigned* a, const unsigned* b) {
    asm volatile(
        "mma.sync.aligned.m16n8k16.row.col.f32.f16.f16.f32 "
        "{%0,%1,%2,%3}, {%4,%5,%6,%7}, {%8,%9}, {%0,%1,%2,%3};"
        : "+f"(c[0]), "+f"(c[1]), "+f"(c[2]), "+f"(c[3])
        : "r"(a[0]), "r"(a[1]), "r"(a[2]), "r"(a[3]), "r"(b[0]), "r"(b[1]));
}
// ldmatrix x4 (base ISA, sm_75+): matrix i -> reg i; lane supplies row addr.
__device__ __forceinline__ void ldm_x4(unsigned* f, uint32_t addr) {
    asm volatile("ldmatrix.sync.aligned.m8n8.x4.shared.b16 {%0,%1,%2,%3}, [%4];"
        : "=r"(f[0]), "=r"(f[1]), "=r"(f[2]), "=r"(f[3]) : "r"(addr));
}
__device__ __forceinline__ float rsqrt_a(float x) {
    float r;
    asm("rsqrt.approx.f32 %0, %1;" : "=f"(r) : "f"(x));
    return r;
}

// ---- prep: x -> fp16, row sums of squares (fp32), init min/max -------------
__global__ __launch_bounds__(256) void hx_prep(const float* __restrict__ x) {
    if (blockIdx.x == 0 && threadIdx.x == 0) {
        g_max_bits = 0u;
        g_min_bits = 0x7F7FFFFFu;
    }
    int f = blockIdx.x * 256 + threadIdx.x;          // float4 index
    float4 v = ((const float4*)x)[f];

    __half2 p0 = __floats2half2_rn(v.x, v.y);
    __half2 p1 = __floats2half2_rn(v.z, v.w);
    ((uint2*)g_xh)[f] = make_uint2(*(unsigned*)&p0, *(unsigned*)&p1);

    float s = v.x * v.x + v.y * v.y + v.z * v.z + v.w * v.w;
    #pragma unroll
    for (int o = 8; o; o >>= 1) s += __shfl_down_sync(0xffffffffu, s, o, 16);
    if ((threadIdx.x & 15) == 0) g_sq[f >> 4] = s;
}

// ---- main: single-term fp16 HMMA Gram tile. MODE 0: min/max. MODE 1: write.
template <int MODE>
__global__ __launch_bounds__(TPB) void hx_mma(float* __restrict__ out) {
    extern __shared__ char smem[];
    const int tid  = threadIdx.x;
    const int wid  = tid >> 5;
    const int lane = tid & 31;
    const int q    = lane >> 2;    // 0..7
    const int t4   = lane & 3;     // 0..3
    const int wm   = wid >> 2;     // 0..1 : 64-row band
    const int wn   = wid & 3;      // 0..3 : 32-col band

    // Decode block -> (b, ti, tj), ti <= tj
    int bidx = blockIdx.x;
    int b = bidx / PAIRS;
    int p = bidx - b * PAIRS;
    int ti = 0, span = TPD;
    while (p >= span) { p -= span; --span; ++ti; }
    int tj = ti + p;
    const bool diag = (ti == tj);
    const int tibase = ti * TILE, tjbase = tj * TILE;

    float mn = 0.f, inv = 0.f;
    if (MODE == 1) {   // constants from pass 0 (launch-ordered)
        float d2min = __uint_as_float(g_min_bits);
        float d2max = __uint_as_float(g_max_bits);
        mn = (d2min > 0.f) ? d2min * rsqrt_a(d2min) : 0.f;
        inv = 1.0f / (d2max * rsqrt_a(d2max) - mn);
    }

    // Load 2 fp16 tiles (A rows ti*128.., B rows tj*128..), [128][64], pitch 144B.
    #pragma unroll
    for (int it = 0; it < 8; ++it) {
        int idx = it * TPB + tid;            // 0..2047
        int t   = idx >> 10;                 // 0 = A, 1 = B
        int rem = idx & 1023;
        int row = rem >> 3;
        int ch  = rem & 7;
        int row0 = (t ? tj : ti) * TILE;
        uint4 v = *(const uint4*)(g_xh + ((size_t)b * BN + row0 + row) * BD + ch * 8);
        *(uint4*)(smem + SM_T + t * TILE_BYTES + row * TILE_PITCH_B + ch * 16) = v;
    }
    if (tid < 128)       ((float*)(smem + SM_SQA))[tid]       = g_sq[b * BN + tibase + tid];
    else                 ((float*)(smem + SM_SQB))[tid - 128] = g_sq[b * BN + tjbase + tid - 128];
    __syncthreads();

    // ldmatrix lane addressing.
    // A x4 per mt: matrices (r..r+7,kb) (r+8..r+15,kb) (r..r+7,kb+16) (r+8..,kb+16)
    //   lane row = rbase + (lane & 15), col byte = (lane>>4)*16.
    // B x4 per nt-pair: {B[2j]: (n..n+7, kb), (n..n+7, kb+16)} then same for 2j+1.
    //   lane row = nbase(2j + (lane>>4)) + (lane & 7), col byte = (lane&8)?16:0.
    uint32_t sBase = (uint32_t)__cvta_generic_to_shared(smem + SM_T);
    uint32_t aAddr[4], bAddr[2];
    {
        int aRow = lane & 15;
        int aCol = (lane >> 4) << 4;
        #pragma unroll
        for (int mt = 0; mt < 4; ++mt)
            aAddr[mt] = sBase + (uint32_t)((wm * 64 + mt * 16 + aRow) * TILE_PITCH_B + aCol);
        int bRow = lane & 7;
        int bCol = (lane & 8) ? 16 : 0;
        int bSel = (lane >> 4) & 1;
        #pragma unroll
        for (int j = 0; j < 2; ++j) {
            int n0 = wn * 32 + (2 * j + bSel) * 8 + bRow;
            bAddr[j] = sBase + (uint32_t)(TILE_BYTES + n0 * TILE_PITCH_B + bCol);
        }
    }

    float acc[4][4][4];
    #pragma unroll
    for (int i = 0; i < 4; ++i)
        #pragma unroll
        for (int j = 0; j < 4; ++j)
            #pragma unroll
            for (int e = 0; e < 4; ++e) acc[i][j][e] = 0.f;

    // Mainloop: per kc, 6 ldmatrix.x4 + 16 HMMA per warp; 4 kc total.
    #pragma unroll
    for (int kc = 0; kc < 4; ++kc) {
        unsigned A[4][4], B[4][2];
        #pragma unroll
        for (int mt = 0; mt < 4; ++mt) ldm_x4(A[mt], aAddr[mt] + kc * 32);
        {
            unsigned t0[4], t1[4];
            ldm_x4(t0, bAddr[0] + kc * 32);
            ldm_x4(t1, bAddr[1] + kc * 32);
            B[0][0] = t0[0]; B[0][1] = t0[1]; B[1][0] = t0[2]; B[1][1] = t0[3];
            B[2][0] = t1[0]; B[2][1] = t1[1]; B[3][0] = t1[2]; B[3][1] = t1[3];
        }
        #pragma unroll
        for (int mt = 0; mt < 4; ++mt)
            #pragma unroll
            for (int nt = 0; nt < 4; ++nt) mma16816(acc[mt][nt], A[mt], B[nt]);
    }

    // Per-thread row/col sums of squares.
    const float* sqa = (const float*)(smem + SM_SQA);
    const float* sqb = (const float*)(smem + SM_SQB);
    float sr0[4], sr1[4], sc0[4], sc1[4];
    #pragma unroll
    for (int mt = 0; mt < 4; ++mt) {
        sr0[mt] = sqa[wm * 64 + mt * 16 + q];
        sr1[mt] = sqa[wm * 64 + mt * 16 + q + 8];
    }
    #pragma unroll
    for (int nt = 0; nt < 4; ++nt) {
        sc0[nt] = sqb[wn * 32 + nt * 8 + t4 * 2];
        sc1[nt] = sqb[wn * 32 + nt * 8 + t4 * 2 + 1];
    }

    if (MODE == 0) {
        float tmax = 0.f, tmin = 3.402823466e38f;
        #pragma unroll
        for (int mt = 0; mt < 4; ++mt)
            #pragma unroll
            for (int nt = 0; nt < 4; ++nt) {
                float d00 = fmaxf(fmaf(-2.f, acc[mt][nt][0], sr0[mt] + sc0[nt]), 0.f);
                float d01 = fmaxf(fmaf(-2.f, acc[mt][nt][1], sr0[mt] + sc1[nt]), 0.f);
                float d10 = fmaxf(fmaf(-2.f, acc[mt][nt][2], sr1[mt] + sc0[nt]), 0.f);
                float d11 = fmaxf(fmaf(-2.f, acc[mt][nt][3], sr1[mt] + sc1[nt]), 0.f);
                tmax = fmaxf(tmax, fmaxf(fmaxf(d00, d01), fmaxf(d10, d11)));
                tmin = fminf(tmin, fminf(fminf(d00, d01), fminf(d10, d11)));
            }
        #pragma unroll
        for (int o = 16; o; o >>= 1) {
            tmax = fmaxf(tmax, __shfl_xor_sync(0xffffffffu, tmax, o));
            tmin = fminf(tmin, __shfl_xor_sync(0xffffffffu, tmin, o));
        }
        if (lane == 0) {
            atomicMax(&g_max_bits, __float_as_uint(tmax));
            atomicMin(&g_min_bits, __float_as_uint(tmin));
        }
        return;
    }

    // MODE 1: normalize in registers, store main tile, stage + store mirror.
    float* ob = out + (size_t)b * BN * BN;
    #pragma unroll
    for (int mt = 0; mt < 4; ++mt) {
        int r0 = wm * 64 + mt * 16 + q, r1 = r0 + 8;
        #pragma unroll
        for (int nt = 0; nt < 4; ++nt) {
            int c0 = wn * 32 + nt * 8 + t4 * 2;
            float d2, d;
            d2 = fmaf(-2.f, acc[mt][nt][0], sr0[mt] + sc0[nt]);
            d  = (d2 > 0.f) ? d2 * rsqrt_a(d2) : 0.f;
            acc[mt][nt][0] = (diag && r0 == c0)     ? 1.0f : (d - mn) * inv;
            d2 = fmaf(-2.f, acc[mt][nt][1], sr0[mt] + sc1[nt]);
            d  = (d2 > 0.f) ? d2 * rsqrt_a(d2) : 0.f;
            acc[mt][nt][1] = (diag && r0 == c0 + 1) ? 1.0f : (d - mn) * inv;
            d2 = fmaf(-2.f, acc[mt][nt][2], sr1[mt] + sc0[nt]);
            d  = (d2 > 0.f) ? d2 * rsqrt_a(d2) : 0.f;
            acc[mt][nt][2] = (diag && r1 == c0)     ? 1.0f : (d - mn) * inv;
            d2 = fmaf(-2.f, acc[mt][nt][3], sr1[mt] + sc1[nt]);
            d  = (d2 > 0.f) ? d2 * rsqrt_a(d2) : 0.f;
            acc[mt][nt][3] = (diag && r1 == c0 + 1) ? 1.0f : (d - mn) * inv;
            *(float2*)(ob + (size_t)(tibase + r0) * BN + tjbase + c0) =
                make_float2(acc[mt][nt][0], acc[mt][nt][1]);
            *(float2*)(ob + (size_t)(tibase + r1) * BN + tjbase + c0) =
                make_float2(acc[mt][nt][2], acc[mt][nt][3]);
        }
    }

    if (!diag) {
        __syncthreads();                     // tiles dead -> reuse as stage
        float* st = (float*)(smem + SM_STT); // [col][row], pitch 136
        #pragma unroll
        for (int mt = 0; mt < 4; ++mt) {
            int r0 = wm * 64 + mt * 16 + q, r1 = r0 + 8;
            #pragma unroll
            for (int nt = 0; nt < 4; ++nt) {
                int c0 = wn * 32 + nt * 8 + t4 * 2;
                st[(c0)     * STT_PITCH + r0] = acc[mt][nt][0];
                st[(c0 + 1) * STT_PITCH + r0] = acc[mt][nt][1];
                st[(c0)     * STT_PITCH + r1] = acc[mt][nt][2];
                st[(c0 + 1) * STT_PITCH + r1] = acc[mt][nt][3];
            }
        }
        __syncthreads();
        #pragma unroll
        for (int i = 0; i < 16; ++i) {
            int idx = i * TPB + tid;
            int mc = idx >> 5, g = idx & 31;
            float4 w = *(const float4*)(st + mc * STT_PITCH + g * 4);
            *(float4*)(ob + (size_t)(tjbase + mc) * BN + tibase + g * 4) = w;
        }
    }
}

extern "C" void kernel_launch(void* const* d_in, const int* in_sizes, int n_in,
                              void* d_out, int out_size) {
    const float* x = (const float*)d_in[0];
    float* out = (float*)d_out;

    cudaFuncSetAttribute(hx_mma<0>, cudaFuncAttributeMaxDynamicSharedMemorySize, SM_TOTAL);
    cudaFuncSetAttribute(hx_mma<1>, cudaFuncAttributeMaxDynamicSharedMemorySize, SM_TOTAL);

    hx_prep<<<(NB * BN * BD / 4) / 256, 256>>>(x);     // fp16 convert + sq + init
    hx_mma<0><<<NBLK, TPB, SM_TOTAL>>>(out);           // global min/max of d2
    hx_mma<1><<<NBLK, TPB, SM_TOTAL>>>(out);           // recompute + normalize + write
}